// round 15
// baseline (speedup 1.0000x reference)
#include <cuda_runtime.h>
#include <cuda_bf16.h>
#include <cstdint>

#define HH 16
#define SS 2048
#define DD 128
#define BM 128
#define BN 64
#define NT 256
#define NELEM (2 * HH * SS * DD)

// ---- device scratch: split K and transposed-split V (bf16 hi/lo) ----
__device__ __nv_bfloat16 g_Khi[NELEM];
__device__ __nv_bfloat16 g_Klo[NELEM];
__device__ __nv_bfloat16 g_VThi[NELEM];   // [bh][d][s]
__device__ __nv_bfloat16 g_VTlo[NELEM];

// ---- main-kernel smem layout (bytes) ----
#define OFF_AMCX 0                     // 2 bufs x (am 256B + cx 256B)
#define OFF_QHI  1024                  // 128 rows x 256B
#define OFF_QLO  33792
#define OFF_KV   66560                 // 2 bufs x 64KB: [KHI 16K][KLO 16K][VHI 16K][VLO 16K]
#define SMEM_TOTAL 197632

__device__ __forceinline__ uint32_t smem_u32(const void* p){
    uint32_t a;
    asm("{ .reg .u64 t; cvta.to.shared.u64 t, %1; cvt.u32.u64 %0, t; }" : "=r"(a) : "l"(p));
    return a;
}
__device__ __forceinline__ void split2(float x, float y, uint32_t& hi, uint32_t& lo){
    __nv_bfloat162 h = __floats2bfloat162_rn(x, y);
    __nv_bfloat162 l = __floats2bfloat162_rn(x - __bfloat162float(h.x), y - __bfloat162float(h.y));
    hi = *reinterpret_cast<uint32_t*>(&h);
    lo = *reinterpret_cast<uint32_t*>(&l);
}
__device__ __forceinline__ void mma_bf16(float* d, const uint32_t* a, uint32_t b0, uint32_t b1){
    asm("mma.sync.aligned.m16n8k16.row.col.f32.bf16.bf16.f32 "
        "{%0,%1,%2,%3}, {%4,%5,%6,%7}, {%8,%9}, {%0,%1,%2,%3};"
        : "+f"(d[0]), "+f"(d[1]), "+f"(d[2]), "+f"(d[3])
        : "r"(a[0]), "r"(a[1]), "r"(a[2]), "r"(a[3]), "r"(b0), "r"(b1));
}
__device__ __forceinline__ void ldsm4(uint32_t* r, uint32_t addr){
    asm volatile("ldmatrix.sync.aligned.m8n8.x4.shared.b16 {%0,%1,%2,%3}, [%4];"
        : "=r"(r[0]), "=r"(r[1]), "=r"(r[2]), "=r"(r[3]) : "r"(addr));
}
__device__ __forceinline__ void cpa16(uint32_t dst, const void* src){
    asm volatile("cp.async.cg.shared.global [%0], [%1], 16;" :: "r"(dst), "l"(src));
}
__device__ __forceinline__ void cpa8(uint32_t dst, const void* src){
    asm volatile("cp.async.ca.shared.global [%0], [%1], 8;" :: "r"(dst), "l"(src));
}
#define CP_COMMIT() asm volatile("cp.async.commit_group;" ::: "memory")
#define CP_WAIT0()  asm volatile("cp.async.wait_group 0;" ::: "memory")
#define CP_WAIT1()  asm volatile("cp.async.wait_group 1;" ::: "memory")

// =================== prepass kernels ===================
__global__ void prep_k_kernel(const float* __restrict__ K){
    size_t i = (size_t)blockIdx.x * 256 + threadIdx.x;   // float4 index
    float4 v = ((const float4*)K)[i];
    uint32_t h0, l0, h1, l1;
    split2(v.x, v.y, h0, l0);
    split2(v.z, v.w, h1, l1);
    ((uint2*)g_Khi)[i] = make_uint2(h0, h1);
    ((uint2*)g_Klo)[i] = make_uint2(l0, l1);
}
__global__ void prep_v_kernel(const float* __restrict__ V){
    __shared__ float ts[32][33];
    const int bh = blockIdx.z, d0 = blockIdx.y * 32, s0 = blockIdx.x * 32;
    const int t = threadIdx.x, i = t >> 3, j4 = (t & 7) * 4;
    const float* Vp = V + ((size_t)bh * SS + s0) * DD + d0;
    float4 v = *(const float4*)(Vp + (size_t)i * DD + j4);
    ts[i][j4] = v.x; ts[i][j4 + 1] = v.y; ts[i][j4 + 2] = v.z; ts[i][j4 + 3] = v.w;
    __syncthreads();
    float a = ts[j4][i], b = ts[j4 + 1][i], c = ts[j4 + 2][i], d = ts[j4 + 3][i];
    uint32_t h0, l0, h1, l1;
    split2(a, b, h0, l0);
    split2(c, d, h1, l1);
    size_t dst = ((size_t)bh * DD + d0 + i) * SS + s0 + j4;
    *(uint2*)(g_VThi + dst) = make_uint2(h0, h1);
    *(uint2*)(g_VTlo + dst) = make_uint2(l0, l1);
}

// =================== main kernel helpers ===================
__device__ __forceinline__ void issue_loads(const __nv_bfloat16* Khb, const __nv_bfloat16* Klb,
                                            const __nv_bfloat16* Vhb, const __nv_bfloat16* Vlb,
                                            const float* AM, const float* CTX, size_t bS,
                                            int kbase, int buf, uint32_t sb, int tid)
{
    const uint32_t kv = sb + OFF_KV + (uint32_t)buf * 65536u;
    #pragma unroll
    for (int i = 0; i < 4; ++i){                      // K: 64 rows x 16 chunks
        int flat = tid + i * NT;
        int r = flat >> 4, c = flat & 15;
        uint32_t o = (uint32_t)r * 256u + ((((uint32_t)c) ^ ((uint32_t)r & 7u)) << 4);
        cpa16(kv + o,          (const char*)(Khb + (size_t)(kbase + r) * DD) + c * 16);
        cpa16(kv + 16384u + o, (const char*)(Klb + (size_t)(kbase + r) * DD) + c * 16);
    }
    #pragma unroll
    for (int i = 0; i < 4; ++i){                      // VT: 128 rows x 8 chunks
        int flat = tid + i * NT;
        int d = flat >> 3, c = flat & 7;
        uint32_t o = (uint32_t)d * 128u + ((((uint32_t)c) ^ ((uint32_t)d & 7u)) << 4);
        cpa16(kv + 32768u + o, (const char*)(Vhb + (size_t)d * SS + kbase) + c * 16);
        cpa16(kv + 49152u + o, (const char*)(Vlb + (size_t)d * SS + kbase) + c * 16);
    }
    if (tid < 32)       cpa8(sb + OFF_AMCX + buf * 512 + tid * 8,              AM  + bS + kbase + 2 * tid);
    else if (tid < 64)  cpa8(sb + OFF_AMCX + buf * 512 + 256 + (tid - 32) * 8, CTX + bS + kbase + 2 * (tid - 32));
    CP_COMMIT();
}

__global__ __launch_bounds__(NT, 1)
void attn_hmma_kernel(const float* __restrict__ Q,
                      const float* __restrict__ AM,
                      const float* __restrict__ HM,
                      const float* __restrict__ CTX,
                      float* __restrict__ out)
{
    extern __shared__ char sm[];
    const uint32_t sb = smem_u32(sm);
    const int tid = threadIdx.x, wid = tid >> 5, lane = tid & 31;

    const int it = (gridDim.x - 1) - blockIdx.x;   // heavy q-tiles first
    const int h = blockIdx.y, b = blockIdx.z;
    const int bh = b * HH + h;
    const int q0 = it * BM;
    const int nt = 2 * (it + 1);

    const float* Qp = Q + ((size_t)bh * SS + q0) * DD;
    const __nv_bfloat16* Khb = g_Khi  + (size_t)bh * SS * DD;
    const __nv_bfloat16* Klb = g_Klo  + (size_t)bh * SS * DD;
    const __nv_bfloat16* Vhb = g_VThi + (size_t)bh * SS * DD;
    const __nv_bfloat16* Vlb = g_VTlo + (size_t)bh * SS * DD;
    const size_t bS = (size_t)b * SS;

    // ---- prologue: start tile-0 streaming, overlap with Q load+split ----
    issue_loads(Khb, Klb, Vhb, Vlb, AM, CTX, bS, 0, 0, sb, tid);
    {
        const float4* Qg = (const float4*)Qp;
        #pragma unroll
        for (int i = 0; i < 16; ++i){
            int flat = tid + i * NT;
            int r = flat >> 5, g = flat & 31;
            float4 v = Qg[flat];
            uint32_t h0, l0, h1, l1;
            split2(v.x, v.y, h0, l0);
            split2(v.z, v.w, h1, l1);
            uint32_t o = (uint32_t)r * 256u
                       + ((((uint32_t)(g >> 1)) ^ ((uint32_t)r & 7u)) << 4)
                       + (((uint32_t)(g & 1)) << 3);
            *(uint2*)(sm + OFF_QHI + o) = make_uint2(h0, h1);
            *(uint2*)(sm + OFF_QLO + o) = make_uint2(l0, l1);
        }
    }

    const int rowA = 16 * wid + (lane & 15);
    const uint32_t qbh = sb + OFF_QHI + rowA * 256;
    const uint32_t qbl = sb + OFF_QLO + rowA * 256;
    const uint32_t swA = rowA & 7, hi4 = lane >> 4;
    const int rB  = (lane & 7) + ((lane >> 4) & 1) * 8;
    const uint32_t cof = (lane >> 3) & 1;

    const int g    = lane >> 2;
    const int colt = 2 * (lane & 3);
    const int qg0 = q0 + 16 * wid + g;
    const int qg1 = qg0 + 8;

    float oacc[16][4];
    #pragma unroll
    for (int i = 0; i < 16; ++i)
        #pragma unroll
        for (int j = 0; j < 4; ++j) oacc[i][j] = 0.f;
    float z0t = 0.f, z1t = 0.f;

    for (int jt = 0; jt < nt; ++jt){
        const int kbase = jt * BN;
        const int cur = jt & 1;
        const uint32_t kvb = sb + OFF_KV + (uint32_t)cur * 65536u;

        __syncthreads();      // all warps done reading buf cur^1 (tile jt-1)
        if (jt + 1 < nt){
            issue_loads(Khb, Klb, Vhb, Vlb, AM, CTX, bS, (jt + 1) * BN, cur ^ 1, sb, tid);
            CP_WAIT1();       // tile jt complete (jt+1 may stay in flight)
        } else {
            CP_WAIT0();
        }
        __syncthreads();      // tile jt visible to all threads

        // causal skip: last k-tile fully masked for warps 0-3 (rows < kbase)
        if (jt == nt - 1 && wid < 4) continue;

        const float* amb = (const float*)(sm + OFF_AMCX + cur * 512);
        const float* cxb = amb + 64;

        // ==== S = Q K^T : full-width, software-pipelined fragment loads ====
        float sacc[8][4];
        #pragma unroll
        for (int i = 0; i < 8; ++i)
            #pragma unroll
            for (int j = 0; j < 4; ++j) sacc[i][j] = 0.f;

        {
            uint32_t ah[2][4], al[2][4], bh4[2][4][4], bl4[2][4][4];
            auto load_qk = [&](int kb, int bi){
                uint32_t coff = (((uint32_t)(2 * kb) + hi4) ^ swA) << 4;
                ldsm4(ah[bi], qbh + coff);
                ldsm4(al[bi], qbl + coff);
                #pragma unroll
                for (int np = 0; np < 4; ++np){
                    int rowB = 16 * np + rB;
                    uint32_t ko = (uint32_t)rowB * 256u
                                + ((((uint32_t)(2 * kb) + cof) ^ ((uint32_t)rowB & 7u)) << 4);
                    ldsm4(bh4[bi][np], kvb + ko);
                    ldsm4(bl4[bi][np], kvb + 16384u + ko);
                }
            };
            load_qk(0, 0);
            #pragma unroll
            for (int kb = 0; kb < 8; ++kb){
                const int cb = kb & 1;
                if (kb < 7) load_qk(kb + 1, cb ^ 1);   // prefetch next kb under this kb's mmas
                #pragma unroll
                for (int np = 0; np < 4; ++np){        // hi x hi
                    mma_bf16(sacc[2 * np],     ah[cb], bh4[cb][np][0], bh4[cb][np][1]);
                    mma_bf16(sacc[2 * np + 1], ah[cb], bh4[cb][np][2], bh4[cb][np][3]);
                }
                #pragma unroll
                for (int np = 0; np < 4; ++np){        // hi x lo
                    mma_bf16(sacc[2 * np],     ah[cb], bl4[cb][np][0], bl4[cb][np][1]);
                    mma_bf16(sacc[2 * np + 1], ah[cb], bl4[cb][np][2], bl4[cb][np][3]);
                }
                #pragma unroll
                for (int np = 0; np < 4; ++np){        // lo x hi
                    mma_bf16(sacc[2 * np],     al[cb], bh4[cb][np][0], bh4[cb][np][1]);
                    mma_bf16(sacc[2 * np + 1], al[cb], bh4[cb][np][2], bh4[cb][np][3]);
                }
            }
        }

        // ==== softmax (m=0): p = exp(s+am), causal zeroing; P -> bf16 hi/lo ====
        uint32_t PH[8][2], PL[8][2];
        #pragma unroll
        for (int j = 0; j < 8; ++j){
            int col = kbase + 8 * j + colt;
            float2 am2 = *(const float2*)&amb[8 * j + colt];
            float2 cx2 = *(const float2*)&cxb[8 * j + colt];
            float p0 = (col     <= qg0) ? __expf(sacc[j][0] + am2.x) : 0.f;
            float p1 = (col + 1 <= qg0) ? __expf(sacc[j][1] + am2.y) : 0.f;
            float p2 = (col     <= qg1) ? __expf(sacc[j][2] + am2.x) : 0.f;
            float p3 = (col + 1 <= qg1) ? __expf(sacc[j][3] + am2.y) : 0.f;
            z0t += p0 + p1;  z1t += p2 + p3;          // Z uses UNSCALED p
            p0 *= cx2.x; p1 *= cx2.y;                 // ctx applied post-softmax
            p2 *= cx2.x; p3 *= cx2.y;
            split2(p0, p1, PH[j][0], PL[j][0]);
            split2(p2, p3, PH[j][1], PL[j][1]);
        }

        // ==== O += P V : 8 steps (kb x hg), software-pipelined V loads ====
        {
            uint32_t vh[2][4][4], vl[2][4][4];
            auto load_v = [&](int step, int bi){
                const int kb = step >> 1, hg = step & 1;
                #pragma unroll
                for (int q = 0; q < 4; ++q){
                    int rowV = 16 * (4 * hg + q) + rB;
                    uint32_t vo = (uint32_t)rowV * 128u
                                + ((((uint32_t)(2 * kb) + cof) ^ ((uint32_t)rowV & 7u)) << 4);
                    ldsm4(vh[bi][q], kvb + 32768u + vo);
                    ldsm4(vl[bi][q], kvb + 49152u + vo);
                }
            };
            load_v(0, 0);
            #pragma unroll
            for (int step = 0; step < 8; ++step){
                const int cb = step & 1;
                const int kb = step >> 1, hg = step & 1;
                if (step < 7) load_v(step + 1, cb ^ 1);   // prefetch under mmas
                uint32_t Ahf[4] = {PH[2 * kb][0], PH[2 * kb][1], PH[2 * kb + 1][0], PH[2 * kb + 1][1]};
                uint32_t Alf[4] = {PL[2 * kb][0], PL[2 * kb][1], PL[2 * kb + 1][0], PL[2 * kb + 1][1]};
                #pragma unroll
                for (int q = 0; q < 4; ++q){              // Ph x Vh
                    int np = 4 * hg + q;
                    mma_bf16(oacc[2 * np],     Ahf, vh[cb][q][0], vh[cb][q][1]);
                    mma_bf16(oacc[2 * np + 1], Ahf, vh[cb][q][2], vh[cb][q][3]);
                }
                #pragma unroll
                for (int q = 0; q < 4; ++q){              // Ph x Vl
                    int np = 4 * hg + q;
                    mma_bf16(oacc[2 * np],     Ahf, vl[cb][q][0], vl[cb][q][1]);
                    mma_bf16(oacc[2 * np + 1], Ahf, vl[cb][q][2], vl[cb][q][3]);
                }
                #pragma unroll
                for (int q = 0; q < 4; ++q){              // Pl x Vh
                    int np = 4 * hg + q;
                    mma_bf16(oacc[2 * np],     Alf, vh[cb][q][0], vh[cb][q][1]);
                    mma_bf16(oacc[2 * np + 1], Alf, vh[cb][q][2], vh[cb][q][3]);
                }
            }
        }
    }

    // ---- epilogue: reduce Z across lane quads, /Z, * head_mask, store ----
    z0t += __shfl_xor_sync(0xffffffffu, z0t, 1);
    z0t += __shfl_xor_sync(0xffffffffu, z0t, 2);
    z1t += __shfl_xor_sync(0xffffffffu, z1t, 1);
    z1t += __shfl_xor_sync(0xffffffffu, z1t, 2);

    const float hm = HM[h];
    const float i0 = hm / z0t, i1 = hm / z1t;
    float* O0 = out + ((size_t)bh * SS + q0 + 16 * wid + g) * DD;
    float* O1 = O0 + 8 * DD;
    #pragma unroll
    for (int nb = 0; nb < 16; ++nb){
        *(float2*)&O0[8 * nb + colt] = make_float2(oacc[nb][0] * i0, oacc[nb][1] * i0);
        *(float2*)&O1[8 * nb + colt] = make_float2(oacc[nb][2] * i1, oacc[nb][3] * i1);
    }
}

extern "C" void kernel_launch(void* const* d_in, const int* in_sizes, int n_in,
                              void* d_out, int out_size)
{
    (void)in_sizes; (void)n_in; (void)out_size;
    const float* Q   = (const float*)d_in[0];
    const float* K   = (const float*)d_in[1];
    const float* V   = (const float*)d_in[2];
    const float* AM  = (const float*)d_in[3];
    const float* HM  = (const float*)d_in[4];
    const float* CTX = (const float*)d_in[5];
    float* out = (float*)d_out;

    cudaFuncSetAttribute(attn_hmma_kernel,
                         cudaFuncAttributeMaxDynamicSharedMemorySize, SMEM_TOTAL);

    prep_k_kernel<<<NELEM / 4 / 256, 256>>>(K);
    prep_v_kernel<<<dim3(SS / 32, DD / 32, 2 * HH), 256>>>(V);

    dim3 grid(SS / BM, HH, 2);
    attn_hmma_kernel<<<grid, NT, SMEM_TOTAL>>>(Q, AM, HM, CTX, out);
}